// round 16
// baseline (speedup 1.0000x reference)
#include <cuda_runtime.h>
#include <cuda_fp16.h>
#include <stdint.h>

#define DIM   64
#define MAX_N 150016           // 100000 users + 50000 items, padded
#define MAX_E 1300000          // actual E = 1,200,000 (incl. flipped copy)

#define SCAN_TB    256
#define SCAN_ITEMS 8           // 2048 elements per block
#define SCAN_CHUNK (SCAN_TB * SCAN_ITEMS)
#define MAX_SCAN_BLOCKS 512

// ---------------------------------------------------------------------------
// Scratch: __device__ globals only (no allocations allowed anywhere).
// Ping-pong buffers hold w = dinv .* x in fp16 (uint2 = 4 halves per lane;
// 16 lanes per 64-dim node row = 128 B contiguous).
// INVARIANT: g_counts == 0 between kernel_launch calls. It is zero-initialized
// at module load, and scan_write_kernel re-zeros every element after use, so
// the invariant holds on the first call and on every graph replay.
// ---------------------------------------------------------------------------
__device__ uint2  g_bufA[MAX_N * 16];    // ping (w0, then w2)
__device__ uint2  g_bufB[MAX_N * 16];    // pong (w1)
__device__ float4 g_dinvs[MAX_N];        // (dinv, dinv^2, sqrt(deg), 0); 0s if isolated
__device__ int    g_counts[MAX_N];       // degree histogram (zero between calls)
__device__ int    g_offsets[MAX_N + 1];  // CSR row pointers (by dst)
__device__ int    g_pos[MAX_N];          // scatter cursors
__device__ int    g_src[MAX_E];          // CSR: source node per slot
__device__ int    g_blocksums[MAX_SCAN_BLOCKS];

// ---------------------------------------------------------------------------
// 1) histogram of destinations (counts are zero on entry per invariant)
// ---------------------------------------------------------------------------
__global__ void count_kernel(const int* __restrict__ edge, int E) {
    int e = blockIdx.x * blockDim.x + threadIdx.x;
    if (e < E) atomicAdd(&g_counts[edge[E + e]], 1);
}

// ---------------------------------------------------------------------------
// 2a) per-block partial sums of counts; also emits g_dinvs (counts already
//     streaming here — one rsqrt/sqrt + one coalesced float4 store each).
// ---------------------------------------------------------------------------
__global__ __launch_bounds__(SCAN_TB)
void scan_partial_kernel(int n) {
    __shared__ int warp_sums[SCAN_TB / 32];
    const int base = blockIdx.x * SCAN_CHUNK;
    const int t = threadIdx.x;

    int s = 0;
    #pragma unroll
    for (int i = 0; i < SCAN_ITEMS; i++) {
        int idx = base + i * SCAN_TB + t;       // coalesced
        if (idx < n) {
            int c = g_counts[idx];
            s += c;
            float d  = (c > 0) ? rsqrtf((float)c) : 0.0f;
            float sd = (c > 0) ? sqrtf((float)c)  : 0.0f;
            g_dinvs[idx] = make_float4(d, d * d, sd, 0.0f);
        }
    }
    #pragma unroll
    for (int o = 16; o > 0; o >>= 1) s += __shfl_down_sync(0xffffffffu, s, o);
    if ((t & 31) == 0) warp_sums[t >> 5] = s;
    __syncthreads();
    if (t < SCAN_TB / 32) {
        int v = warp_sums[t];
        #pragma unroll
        for (int o = SCAN_TB / 64; o > 0; o >>= 1) v += __shfl_down_sync(0xffffffffu, v, o);
        if (t == 0) g_blocksums[blockIdx.x] = v;
    }
}

// ---------------------------------------------------------------------------
// 2b) per-block exclusive scan -> offsets/pos. Block offset computed in-kernel
//     (warp 1 strides over preceding blocksums while others load). Shuffle
//     scan: 2 __syncthreads total. Also restores g_counts == 0.
// ---------------------------------------------------------------------------
__global__ __launch_bounds__(SCAN_TB)
void scan_write_kernel(int n, int E) {
    __shared__ int sh_warp[SCAN_TB / 32];   // 8 warp sums
    __shared__ int sh_off;                  // block offset
    const int base = blockIdx.x * SCAN_CHUNK;
    const int t    = threadIdx.x;
    const int lane = t & 31;
    const int wid  = t >> 5;
    const int lo   = base + t * SCAN_ITEMS;

    // load this thread's 8 counts, thread-local sum
    int c[SCAN_ITEMS];
    int s = 0;
    #pragma unroll
    for (int i = 0; i < SCAN_ITEMS; i++) {
        int idx = lo + i;
        c[i] = (idx < n) ? g_counts[idx] : 0;
        s += c[i];
    }

    // per-warp inclusive shuffle scan of thread sums
    int incl = s;
    #pragma unroll
    for (int o = 1; o < 32; o <<= 1) {
        int v = __shfl_up_sync(0xffffffffu, incl, o);
        if (lane >= o) incl += v;
    }
    if (lane == 31) sh_warp[wid] = incl;

    // warp 1: block offset = sum of preceding blocksums (<= gridDim.x-1 ints)
    if (wid == 1) {
        int s2 = 0;
        for (int i = lane; i < blockIdx.x; i += 32) s2 += g_blocksums[i];
        #pragma unroll
        for (int o = 16; o > 0; o >>= 1) s2 += __shfl_down_sync(0xffffffffu, s2, o);
        if (lane == 0) sh_off = s2;
    }
    __syncthreads();

    // warp 0 lanes 0..7: inclusive scan of the 8 warp sums
    if (t < SCAN_TB / 32) {
        int v = sh_warp[t];
        #pragma unroll
        for (int o = 1; o < SCAN_TB / 32; o <<= 1) {
            int u = __shfl_up_sync(0xffu, v, o);
            if (t >= o) v += u;
        }
        sh_warp[t] = v;
    }
    __syncthreads();

    int prefix = sh_off + ((wid == 0) ? 0 : sh_warp[wid - 1]) + (incl - s);
    #pragma unroll
    for (int i = 0; i < SCAN_ITEMS; i++) {
        int idx = lo + i;
        if (idx < n) {
            g_offsets[idx] = prefix;
            g_pos[idx]     = prefix;
            g_counts[idx]  = 0;                 // restore invariant for next call
            prefix += c[i];
        }
    }
    if (blockIdx.x == 0 && t == 0) g_offsets[n] = E;
}

// ---------------------------------------------------------------------------
// 3+4) fused: scatter edges into CSR slots AND init w0 (independent work).
// ---------------------------------------------------------------------------
__global__ void fill_init_kernel(const int* __restrict__ edge, int E,
                                 const float* __restrict__ ue,
                                 const float* __restrict__ ie,
                                 int nu_elems, int total) {
    int i = blockIdx.x * blockDim.x + threadIdx.x;
    if (i < E) {
        int r = edge[i];
        int c = edge[E + i];
        int slot = atomicAdd(&g_pos[c], 1);
        g_src[slot] = r;
    }
    if (i < total) {
        float v = (i < nu_elems) ? ue[i] : ie[i - nu_elems];
        reinterpret_cast<__half*>(g_bufA)[i] = __float2half_rn(v * g_dinvs[i >> 6].x);
    }
}

// ---------------------------------------------------------------------------
// 5) pull pass: S[n] = sum_{k in csr(n)} W[src[k]]  (fp16 payload, fp32 accum)
//    MID:  Y[n] = fp16( dinv^2 * S )
//    LAST: out[n] = 0.25*( x0 + sqrtdeg*(w1+w2) + dinv*S )
//    16 threads (half-warp) per node, one uint2 (4 halves) lane each;
//    2-edge unroll with dual accumulators (proven R9 loop).
// ---------------------------------------------------------------------------
__device__ __forceinline__ void acc_u2(const uint2 u, float& x, float& y, float& z, float& w) {
    float2 f0 = __half22float2(*reinterpret_cast<const __half2*>(&u.x));
    float2 f1 = __half22float2(*reinterpret_cast<const __half2*>(&u.y));
    x += f0.x; y += f0.y; z += f1.x; w += f1.y;
}

template <bool A_TO_B, bool LAST>
__global__ __launch_bounds__(256)
void pull_kernel(int N, int nu_nodes,
                 const float* __restrict__ ue, const float* __restrict__ ie,
                 float* __restrict__ out) {
    int t = blockIdx.x * blockDim.x + threadIdx.x;
    int node = t >> 4;
    if (node >= N) return;
    int lane = t & 15;

    const uint2* __restrict__ X = A_TO_B ? g_bufA : g_bufB;
    uint2*       __restrict__ Y = A_TO_B ? g_bufB : g_bufA;

    const int beg = g_offsets[node];
    const int end = g_offsets[node + 1];

    float a0x = 0.f, a0y = 0.f, a0z = 0.f, a0w = 0.f;
    float a1x = 0.f, a1y = 0.f, a1z = 0.f, a1w = 0.f;

    int k = beg;
    for (; k + 1 < end; k += 2) {
        int s0 = g_src[k];
        int s1 = g_src[k + 1];
        uint2 u0 = X[(size_t)s0 * 16 + lane];
        uint2 u1 = X[(size_t)s1 * 16 + lane];
        acc_u2(u0, a0x, a0y, a0z, a0w);
        acc_u2(u1, a1x, a1y, a1z, a1w);
    }
    if (k < end) {
        uint2 u0 = X[(size_t)g_src[k] * 16 + lane];
        acc_u2(u0, a0x, a0y, a0z, a0w);
    }

    float sx = a0x + a1x, sy = a0y + a1y, sz = a0z + a1z, sw = a0w + a1w;

    float4 dv = g_dinvs[node];          // (dinv, dinv^2, sqrtdeg, 0)

    if (!LAST) {
        __half2 p0 = __floats2half2_rn(dv.y * sx, dv.y * sy);
        __half2 p1 = __floats2half2_rn(dv.y * sz, dv.y * sw);
        uint2 st;
        st.x = *reinterpret_cast<unsigned int*>(&p0);
        st.y = *reinterpret_cast<unsigned int*>(&p1);
        Y[(size_t)node * 16 + lane] = st;
    } else {
        // x0 from inputs; w1 in bufB, w2 in bufA (== X for this launch)
        const float* x0row = (node < nu_nodes)
            ? (ue + (size_t)node * DIM)
            : (ie + (size_t)(node - nu_nodes) * DIM);
        float4 x0 = *reinterpret_cast<const float4*>(x0row + (lane << 2));

        uint2 u1 = g_bufB[(size_t)node * 16 + lane];
        uint2 u2 = g_bufA[(size_t)node * 16 + lane];
        float w1x = 0.f, w1y = 0.f, w1z = 0.f, w1w = 0.f;
        float w2x = 0.f, w2y = 0.f, w2z = 0.f, w2w = 0.f;
        acc_u2(u1, w1x, w1y, w1z, w1w);
        acc_u2(u2, w2x, w2y, w2z, w2w);

        float4 r;
        r.x = 0.25f * (x0.x + dv.z * (w1x + w2x) + dv.x * sx);
        r.y = 0.25f * (x0.y + dv.z * (w1y + w2y) + dv.x * sy);
        r.z = 0.25f * (x0.z + dv.z * (w1z + w2z) + dv.x * sz);
        r.w = 0.25f * (x0.w + dv.z * (w1w + w2w) + dv.x * sw);
        *reinterpret_cast<float4*>(out + (size_t)node * DIM + (lane << 2)) = r;
    }
}

// ---------------------------------------------------------------------------
// kernel_launch
// inputs: [0] user_emb f32 [100000*64], [1] item_emb f32 [50000*64],
//         [2] edge_index int32 [2 * 1200000]
// output: f32 [150000*64]
// ---------------------------------------------------------------------------
extern "C" void kernel_launch(void* const* d_in, const int* in_sizes, int n_in,
                              void* d_out, int out_size) {
    const float* user_emb = (const float*)d_in[0];
    const float* item_emb = (const float*)d_in[1];
    const int*   edge     = (const int*)d_in[2];
    float*       out      = (float*)d_out;

    const int nu_elems = in_sizes[0];
    const int ni_elems = in_sizes[1];
    const int E        = in_sizes[2] / 2;
    const int NU       = nu_elems / DIM;
    const int N        = NU + ni_elems / DIM;
    const int total    = N * DIM;

    const int TB = 256;
    const int eblk  = (E + TB - 1) / TB;
    const int tblk  = (total + TB - 1) / TB;     // total > E, covers both fused loops
    const int pullb = (N * 16 + TB - 1) / TB;
    const int scanb = (N + SCAN_CHUNK - 1) / SCAN_CHUNK;

    // CSR build (by destination); counts arrive zero per the self-clean invariant
    count_kernel<<<eblk, TB>>>(edge, E);
    scan_partial_kernel<<<scanb, SCAN_TB>>>(N);            // + g_dinvs
    scan_write_kernel<<<scanb, SCAN_TB>>>(N, E);           // + in-kernel blocksum prefix
    fill_init_kernel<<<tblk, TB>>>(edge, E, user_emb, item_emb, nu_elems, total);

    // 3 propagation layers; out materialized only in the last one
    pull_kernel<true , false><<<pullb, TB>>>(N, NU, user_emb, item_emb, out); // A->B (w1)
    pull_kernel<false, false><<<pullb, TB>>>(N, NU, user_emb, item_emb, out); // B->A (w2)
    pull_kernel<true , true ><<<pullb, TB>>>(N, NU, user_emb, item_emb, out); // A-> out
}